// round 3
// baseline (speedup 1.0000x reference)
#include <cuda_runtime.h>
#include <cstddef>

// ---------------- problem constants ----------------
#define BB   4
#define NQ   4096
#define NV   9216
#define EE   768
#define NH   8
#define NP   4
#define HD   96
#define HF   96
#define WF   96

#define BQ   (BB * NQ)   // 16384 query rows
#define BV   (BB * NV)   // 36864 feat rows
#define NCAT 128         // padded N for offset+attn projection (64 + 32 + 32 pad)

// ---------------- scratch (device globals; no allocation allowed) ----------------
__device__ float g_qnorm[(size_t)BQ * EE];      // LN(query)
__device__ float g_fnorm[(size_t)BV * EE];      // LN(feat)
__device__ float g_value[(size_t)BV * EE];      // fnorm @ W_value + b
__device__ float g_raw  [(size_t)BQ * NCAT];    // qnorm @ [W_off|W_attn]
__device__ float g_wcat [(size_t)EE * NCAT];    // packed weights (zero padded)
__device__ float g_bcat [NCAT];
__device__ float g_loc  [(size_t)BQ * NH * NP * 2];
__device__ float g_aw   [(size_t)BQ * NH * NP];
__device__ float g_msda [(size_t)BQ * EE];      // sampled output

// ---------------- kernel: pack W_off / W_attn into padded [E][128] ----------------
__global__ void prep_kernel(const float* __restrict__ W_off, const float* __restrict__ b_off,
                            const float* __restrict__ W_attn, const float* __restrict__ b_attn)
{
    int idx = blockIdx.x * blockDim.x + threadIdx.x;
    if (idx < EE * NCAT) {
        int k = idx / NCAT, n = idx % NCAT;
        float v = 0.f;
        if (n < 64)        v = W_off[k * 64 + n];
        else if (n < 96)   v = W_attn[k * 32 + (n - 64)];
        g_wcat[idx] = v;
    }
    if (idx < NCAT) {
        float v = 0.f;
        if (idx < 64)      v = b_off[idx];
        else if (idx < 96) v = b_attn[idx - 64];
        g_bcat[idx] = v;
    }
}

// ---------------- kernel: LayerNorm over E=768, one block per row ----------------
__global__ void ln_kernel(const float* __restrict__ x, const float* __restrict__ w,
                          const float* __restrict__ b, float* __restrict__ y)
{
    __shared__ float rs[8], rq[8];
    int row = blockIdx.x;
    int t = threadIdx.x;                      // 256 threads
    const float* xr = x + (size_t)row * EE;
    float v0 = xr[t], v1 = xr[t + 256], v2 = xr[t + 512];
    float s = v0 + v1 + v2;
    float q = v0 * v0 + v1 * v1 + v2 * v2;
#pragma unroll
    for (int o = 16; o > 0; o >>= 1) {
        s += __shfl_down_sync(0xffffffffu, s, o);
        q += __shfl_down_sync(0xffffffffu, q, o);
    }
    int wid = t >> 5, lane = t & 31;
    if (lane == 0) { rs[wid] = s; rq[wid] = q; }
    __syncthreads();
    float S = 0.f, Q = 0.f;
#pragma unroll
    for (int i = 0; i < 8; i++) { S += rs[i]; Q += rq[i]; }
    const float inv = 1.0f / (float)EE;
    float mean = S * inv;
    float var  = Q * inv - mean * mean;
    float r    = rsqrtf(var + 1e-6f);
    float* yr = y + (size_t)row * EE;
    yr[t]       = (v0 - mean) * r * w[t]       + b[t];
    yr[t + 256] = (v1 - mean) * r * w[t + 256] + b[t + 256];
    yr[t + 512] = (v2 - mean) * r * w[t + 512] + b[t + 512];
}

// ---------------- kernel: 128x128x8 tiled fp32 SGEMM, 8x8 microtile ----------------
// C[M,N] = A[M,K] @ B[K,N] + bias[N]; if FUSE: C = qin + gamma*(qn + C)
// Requires M%128==0, N%128==0, K%8==0.
template <bool FUSE>
__global__ void sgemm128(const float* __restrict__ A, const float* __restrict__ Bm,
                         const float* __restrict__ bias, float* __restrict__ C,
                         int M, int N, int K,
                         const float* __restrict__ qn,
                         const float* __restrict__ qin,
                         const float* __restrict__ gamma)
{
    __shared__ float As[8][128];
    __shared__ float Bs[8][128];
    int tid = threadIdx.x;                  // 256
    int tx = tid & 15, ty = tid >> 4;
    int rowBase = blockIdx.y * 128;
    int colBase = blockIdx.x * 128;

    int aRow = tid >> 1;                    // 0..127
    int aK   = (tid & 1) * 4;               // 0 or 4
    int bK   = tid >> 5;                    // 0..7
    int bCol = (tid & 31) * 4;              // 0..124

    const float* Ap = A + (size_t)(rowBase + aRow) * K + aK;
    const float* Bp = Bm + (size_t)bK * N + colBase + bCol;

    float acc[8][8];
#pragma unroll
    for (int i = 0; i < 8; i++)
#pragma unroll
        for (int j = 0; j < 8; j++) acc[i][j] = 0.f;

    for (int kt = 0; kt < K; kt += 8) {
        float4 a4 = *(const float4*)(Ap + kt);
        float4 b4 = *(const float4*)(Bp + (size_t)kt * N);
        As[aK + 0][aRow] = a4.x;
        As[aK + 1][aRow] = a4.y;
        As[aK + 2][aRow] = a4.z;
        As[aK + 3][aRow] = a4.w;
        *(float4*)&Bs[bK][bCol] = b4;
        __syncthreads();
#pragma unroll
        for (int k = 0; k < 8; k++) {
            float ar[8], br[8];
            *(float4*)(ar)     = *(const float4*)&As[k][ty * 8];
            *(float4*)(ar + 4) = *(const float4*)&As[k][ty * 8 + 4];
            *(float4*)(br)     = *(const float4*)&Bs[k][tx * 8];
            *(float4*)(br + 4) = *(const float4*)&Bs[k][tx * 8 + 4];
#pragma unroll
            for (int i = 0; i < 8; i++)
#pragma unroll
                for (int j = 0; j < 8; j++)
                    acc[i][j] += ar[i] * br[j];
        }
        __syncthreads();
    }

#pragma unroll
    for (int i = 0; i < 8; i++) {
        int r = rowBase + ty * 8 + i;
        size_t ro = (size_t)r * N;
#pragma unroll
        for (int j = 0; j < 8; j++) {
            int c = colBase + tx * 8 + j;
            float val = acc[i][j] + bias[c];
            if (FUSE) {
                size_t o = (size_t)r * EE + c;   // N == EE in fused call
                val = qin[o] + gamma[c] * (qn[o] + val);
            }
            C[ro + c] = val;
        }
    }
}

// ---------------- kernel: sampling locations + softmax weights ----------------
// one thread per (b*NQ+q, h)
__global__ void locaw_kernel(const float* __restrict__ refp)
{
    int t = blockIdx.x * blockDim.x + threadIdx.x;
    if (t >= BQ * NH) return;
    int bq = t >> 3;
    int h  = t & 7;
    const float* raw = g_raw + (size_t)bq * NCAT;
    float rx = refp[bq * 2 + 0];
    float ry = refp[bq * 2 + 1];

    float* lp = g_loc + (size_t)t * NP * 2;
    float* ap = g_aw  + (size_t)t * NP;

    // offsets: cols h*8 + p*2 + c ; logits: cols 64 + h*4 + p
    float lg[NP];
    float m = -1e30f;
#pragma unroll
    for (int p = 0; p < NP; p++) {
        lg[p] = raw[64 + h * 4 + p];
        m = fmaxf(m, lg[p]);
    }
    float sum = 0.f;
#pragma unroll
    for (int p = 0; p < NP; p++) { lg[p] = expf(lg[p] - m); sum += lg[p]; }
    float rinv = 1.0f / sum;
#pragma unroll
    for (int p = 0; p < NP; p++) {
        lp[p * 2 + 0] = rx + raw[h * 8 + p * 2 + 0] * (1.0f / (float)WF);
        lp[p * 2 + 1] = ry + raw[h * 8 + p * 2 + 1] * (1.0f / (float)HF);
        ap[p] = lg[p] * rinv;
    }
}

// ---------------- kernel: deformable bilinear sampling ----------------
// one warp per (b*NQ+q, h); lane covers d, d+32, d+64 of HD=96
__global__ void msda_kernel()
{
    int gwarp = (blockIdx.x * blockDim.x + threadIdx.x) >> 5;
    int lane  = threadIdx.x & 31;
    if (gwarp >= BQ * NH) return;
    int bq = gwarp >> 3;
    int h  = gwarp & 7;
    int b  = bq >> 12;              // bq / NQ (NQ=4096)

    const float* lc  = g_loc + (size_t)gwarp * NP * 2;
    const float* awp = g_aw  + (size_t)gwarp * NP;
    const float* vbase = g_value + (size_t)b * NV * EE + (size_t)h * HD;

    float acc0 = 0.f, acc1 = 0.f, acc2 = 0.f;
#pragma unroll
    for (int p = 0; p < NP; p++) {
        float x = lc[p * 2 + 0] * (float)WF - 0.5f;
        float y = lc[p * 2 + 1] * (float)HF - 0.5f;
        float a = awp[p];
        float fx = floorf(x), fy = floorf(y);
        int x0 = (int)fx, y0 = (int)fy;
        float tx = x - fx, ty = y - fy;
        float w00 = (1.f - tx) * (1.f - ty) * a;
        float w01 = tx * (1.f - ty) * a;
        float w10 = (1.f - tx) * ty * a;
        float w11 = tx * ty * a;
#pragma unroll
        for (int c = 0; c < 4; c++) {
            int xi = x0 + (c & 1);
            int yi = y0 + (c >> 1);
            float w = (c == 0) ? w00 : (c == 1) ? w01 : (c == 2) ? w10 : w11;
            if (xi >= 0 && xi < WF && yi >= 0 && yi < HF) {
                const float* v = vbase + (size_t)(yi * WF + xi) * EE;
                acc0 += w * v[lane];
                acc1 += w * v[lane + 32];
                acc2 += w * v[lane + 64];
            }
        }
    }
    float* o = g_msda + (size_t)bq * EE + (size_t)h * HD;
    o[lane]      = acc0;
    o[lane + 32] = acc1;
    o[lane + 64] = acc2;
}

// ---------------- launch ----------------
extern "C" void kernel_launch(void* const* d_in, const int* in_sizes, int n_in,
                              void* d_out, int out_size)
{
    (void)in_sizes; (void)n_in; (void)out_size;
    const float* query  = (const float*)d_in[0];
    const float* refp   = (const float*)d_in[1];
    const float* feat   = (const float*)d_in[2];
    // d_in[3] spatial_shapes, d_in[4] level_start_index: static, unused
    const float* ln_q_w = (const float*)d_in[5];
    const float* ln_q_b = (const float*)d_in[6];
    const float* ln_f_w = (const float*)d_in[7];
    const float* ln_f_b = (const float*)d_in[8];
    const float* W_value= (const float*)d_in[9];
    const float* b_value= (const float*)d_in[10];
    const float* W_off  = (const float*)d_in[11];
    const float* b_off  = (const float*)d_in[12];
    const float* W_attn = (const float*)d_in[13];
    const float* b_attn = (const float*)d_in[14];
    const float* W_out  = (const float*)d_in[15];
    const float* b_out  = (const float*)d_in[16];
    const float* gamma  = (const float*)d_in[17];
    float* out = (float*)d_out;

    float *qnorm, *fnorm, *value, *raw, *wcat, *bcat, *msda;
    cudaGetSymbolAddress((void**)&qnorm, g_qnorm);
    cudaGetSymbolAddress((void**)&fnorm, g_fnorm);
    cudaGetSymbolAddress((void**)&value, g_value);
    cudaGetSymbolAddress((void**)&raw,   g_raw);
    cudaGetSymbolAddress((void**)&wcat,  g_wcat);
    cudaGetSymbolAddress((void**)&bcat,  g_bcat);
    cudaGetSymbolAddress((void**)&msda,  g_msda);

    // 1. pack offset/attn weights (zero-padded to 128 cols)
    prep_kernel<<<(EE * NCAT + 255) / 256, 256>>>(W_off, b_off, W_attn, b_attn);

    // 2. LayerNorms
    ln_kernel<<<BQ, 256>>>(query, ln_q_w, ln_q_b, qnorm);
    ln_kernel<<<BV, 256>>>(feat,  ln_f_w, ln_f_b, fnorm);

    // 3. value projection: [36864,768] = fnorm @ W_value
    {
        dim3 g(EE / 128, BV / 128);
        sgemm128<false><<<g, 256>>>(fnorm, W_value, b_value, value,
                                    BV, EE, EE, nullptr, nullptr, nullptr);
    }

    // 4. offset+attn projection: [16384,128] = qnorm @ wcat
    {
        dim3 g(NCAT / 128, BQ / 128);
        sgemm128<false><<<g, 256>>>(qnorm, wcat, bcat, raw,
                                    BQ, NCAT, EE, nullptr, nullptr, nullptr);
    }

    // 5. sampling locations + softmax attention weights
    locaw_kernel<<<(BQ * NH + 255) / 256, 256>>>(refp);

    // 6. deformable bilinear sampling: 1 warp per (b,q,h)
    msda_kernel<<<(BQ * NH * 32) / 256, 256>>>();

    // 7. output projection + fused residual: d_out = query + gamma*(qnorm + msda@W_out + b_out)
    {
        dim3 g(EE / 128, BQ / 128);
        sgemm128<true><<<g, 256>>>(msda, W_out, b_out, out,
                                   BQ, EE, EE, qnorm, query, gamma);
    }
}

// round 4
// speedup vs baseline: 3.5697x; 3.5697x over previous
#include <cuda_runtime.h>
#include <cuda_bf16.h>
#include <cstdint>
#include <cstddef>

// ---------------- problem constants ----------------
#define BB   4
#define NQ   4096
#define NV   9216
#define EE   768
#define NH   8
#define NP   4
#define HD   96
#define HF   96
#define WF   96

#define BQ   (BB * NQ)   // 16384 query rows
#define BV   (BB * NV)   // 36864 feat rows
#define NCAT 128         // padded N for offset+attn projection

// ---------------- scratch (device globals) ----------------
__device__ float          g_qnorm   [(size_t)BQ * EE];     // LN(query) fp32 (epilogue)
__device__ __nv_bfloat16  g_qnorm_bf[(size_t)BQ * EE];     // LN(query) bf16 (GEMM A)
__device__ __nv_bfloat16  g_fnorm_bf[(size_t)BV * EE];     // LN(feat) bf16 (GEMM A)
__device__ float          g_value   [(size_t)BV * EE];     // value proj fp32
__device__ float          g_raw     [(size_t)BQ * NCAT];   // offset/attn logits fp32
__device__ __nv_bfloat16  g_wv_bf   [(size_t)EE * EE];     // W_value bf16
__device__ __nv_bfloat16  g_wo_bf   [(size_t)EE * EE];     // W_out bf16
__device__ __nv_bfloat16  g_wcat_bf [(size_t)EE * NCAT];   // packed [W_off|W_attn|0] bf16
__device__ float          g_bcat    [NCAT];
__device__ float          g_loc     [(size_t)BQ * NH * NP * 2];
__device__ float          g_aw      [(size_t)BQ * NH * NP];
__device__ __nv_bfloat16  g_msda_bf [(size_t)BQ * EE];     // sampled output bf16

// ---------------- PTX helpers ----------------
__device__ __forceinline__ void ldsm4(uint32_t& r0, uint32_t& r1, uint32_t& r2, uint32_t& r3,
                                      uint32_t addr)
{
    asm volatile("ldmatrix.sync.aligned.m8n8.x4.shared.b16 {%0,%1,%2,%3}, [%4];"
                 : "=r"(r0), "=r"(r1), "=r"(r2), "=r"(r3) : "r"(addr));
}
__device__ __forceinline__ void ldsm4t(uint32_t& r0, uint32_t& r1, uint32_t& r2, uint32_t& r3,
                                       uint32_t addr)
{
    asm volatile("ldmatrix.sync.aligned.m8n8.x4.trans.shared.b16 {%0,%1,%2,%3}, [%4];"
                 : "=r"(r0), "=r"(r1), "=r"(r2), "=r"(r3) : "r"(addr));
}
__device__ __forceinline__ void mma16816(float* c, uint32_t a0, uint32_t a1, uint32_t a2,
                                         uint32_t a3, uint32_t b0, uint32_t b1)
{
    asm volatile("mma.sync.aligned.m16n8k16.row.col.f32.bf16.bf16.f32 "
                 "{%0,%1,%2,%3}, {%4,%5,%6,%7}, {%8,%9}, {%0,%1,%2,%3};"
                 : "+f"(c[0]), "+f"(c[1]), "+f"(c[2]), "+f"(c[3])
                 : "r"(a0), "r"(a1), "r"(a2), "r"(a3), "r"(b0), "r"(b1));
}

// ---------------- kernel: convert weights to bf16 + pack cat weights ----------------
__global__ void cvt_kernel(const float* __restrict__ Wv, const float* __restrict__ Wo,
                           const float* __restrict__ W_off, const float* __restrict__ b_off,
                           const float* __restrict__ W_attn, const float* __restrict__ b_attn)
{
    int idx = blockIdx.x * blockDim.x + threadIdx.x;
    if (idx < EE * EE) {
        g_wv_bf[idx] = __float2bfloat16(Wv[idx]);
        g_wo_bf[idx] = __float2bfloat16(Wo[idx]);
    }
    if (idx < EE * NCAT) {
        int k = idx / NCAT, n = idx % NCAT;
        float v = 0.f;
        if (n < 64)      v = W_off[k * 64 + n];
        else if (n < 96) v = W_attn[k * 32 + (n - 64)];
        g_wcat_bf[idx] = __float2bfloat16(v);
    }
    if (idx < NCAT) {
        float v = 0.f;
        if (idx < 64)      v = b_off[idx];
        else if (idx < 96) v = b_attn[idx - 64];
        g_bcat[idx] = v;
    }
}

// ---------------- kernel: LayerNorm over E=768 ----------------
template <bool WRITE_F32>
__global__ void ln_kernel(const float* __restrict__ x, const float* __restrict__ w,
                          const float* __restrict__ b, float* __restrict__ y,
                          __nv_bfloat16* __restrict__ yb)
{
    __shared__ float rs[8], rq[8];
    int row = blockIdx.x;
    int t = threadIdx.x;                      // 256 threads
    const float* xr = x + (size_t)row * EE;
    float v0 = xr[t], v1 = xr[t + 256], v2 = xr[t + 512];
    float s = v0 + v1 + v2;
    float q = v0 * v0 + v1 * v1 + v2 * v2;
#pragma unroll
    for (int o = 16; o > 0; o >>= 1) {
        s += __shfl_down_sync(0xffffffffu, s, o);
        q += __shfl_down_sync(0xffffffffu, q, o);
    }
    int wid = t >> 5, lane = t & 31;
    if (lane == 0) { rs[wid] = s; rq[wid] = q; }
    __syncthreads();
    float S = 0.f, Q = 0.f;
#pragma unroll
    for (int i = 0; i < 8; i++) { S += rs[i]; Q += rq[i]; }
    const float inv = 1.0f / (float)EE;
    float mean = S * inv;
    float var  = Q * inv - mean * mean;
    float r    = rsqrtf(var + 1e-6f);
    size_t base = (size_t)row * EE;
    float o0 = (v0 - mean) * r * w[t]       + b[t];
    float o1 = (v1 - mean) * r * w[t + 256] + b[t + 256];
    float o2 = (v2 - mean) * r * w[t + 512] + b[t + 512];
    if (WRITE_F32) {
        y[base + t]       = o0;
        y[base + t + 256] = o1;
        y[base + t + 512] = o2;
    }
    yb[base + t]       = __float2bfloat16(o0);
    yb[base + t + 256] = __float2bfloat16(o1);
    yb[base + t + 512] = __float2bfloat16(o2);
}

// ---------------- kernel: 128x128 bf16 tensor-core GEMM ----------------
// C[M,N] = A[M,K](bf16) @ B[K,N](bf16) + bias[N]; FUSE: C = qin + gamma*(qn + C)
// 256 threads = 8 warps (2x4), warp tile 64x32, k-step 16.
template <bool FUSE>
__global__ void __launch_bounds__(256)
gemm_bf16(const __nv_bfloat16* __restrict__ A, const __nv_bfloat16* __restrict__ Bm,
          const float* __restrict__ bias, float* __restrict__ C,
          int M, int N, int K,
          const float* __restrict__ qn, const float* __restrict__ qin,
          const float* __restrict__ gamma)
{
    __shared__ __nv_bfloat16 As[128][24];   // pitch 48B: conflict-free ldmatrix
    __shared__ __nv_bfloat16 Bs[16][136];   // pitch 272B: conflict-free ldmatrix

    int tid = threadIdx.x, warp = tid >> 5, lane = tid & 31;
    int rowBase = blockIdx.y * 128;
    int colBase = blockIdx.x * 128;
    int wm = (warp >> 2) * 64;
    int wn = (warp & 3) * 32;

    // global staging indices
    int aRow = tid >> 1,  aCol = (tid & 1) * 8;   // 128 rows x 16 cols
    int bRow = tid >> 4,  bCol = (tid & 15) * 8;  // 16 rows  x 128 cols
    const __nv_bfloat16* Ag = A  + (size_t)(rowBase + aRow) * K + aCol;
    const __nv_bfloat16* Bg = Bm + (size_t)bRow * N + colBase + bCol;

    // ldmatrix smem addresses
    uint32_t aSm[4], bSm[2];
    {
        int r  = lane & 15;
        int co = (lane >> 4) * 8;
#pragma unroll
        for (int i = 0; i < 4; i++)
            aSm[i] = (uint32_t)__cvta_generic_to_shared(&As[wm + i * 16 + r][co]);
        int k = lane & 15;
#pragma unroll
        for (int j = 0; j < 2; j++)
            bSm[j] = (uint32_t)__cvta_generic_to_shared(&Bs[k][wn + j * 16 + (lane >> 4) * 8]);
    }

    float acc[4][4][4];
#pragma unroll
    for (int i = 0; i < 4; i++)
#pragma unroll
        for (int j = 0; j < 4; j++)
#pragma unroll
            for (int v = 0; v < 4; v++) acc[i][j][v] = 0.f;

    uint4 aR = *(const uint4*)Ag;
    uint4 bR = *(const uint4*)Bg;

    for (int kt = 0; kt < K; kt += 16) {
        *(uint4*)&As[aRow][aCol] = aR;
        *(uint4*)&Bs[bRow][bCol] = bR;
        __syncthreads();
        if (kt + 16 < K) {
            aR = *(const uint4*)(Ag + kt + 16);
            bR = *(const uint4*)(Bg + (size_t)(kt + 16) * N);
        }
        uint32_t af[4][4], bf[2][4];
#pragma unroll
        for (int i = 0; i < 4; i++)
            ldsm4(af[i][0], af[i][1], af[i][2], af[i][3], aSm[i]);
#pragma unroll
        for (int j = 0; j < 2; j++)
            ldsm4t(bf[j][0], bf[j][1], bf[j][2], bf[j][3], bSm[j]);
#pragma unroll
        for (int i = 0; i < 4; i++)
#pragma unroll
            for (int j = 0; j < 4; j++)
                mma16816(acc[i][j], af[i][0], af[i][1], af[i][2], af[i][3],
                         bf[j >> 1][(j & 1) * 2], bf[j >> 1][(j & 1) * 2 + 1]);
        __syncthreads();
    }

    // epilogue
    int g = lane >> 2, tg = lane & 3;
#pragma unroll
    for (int i = 0; i < 4; i++) {
#pragma unroll
        for (int j = 0; j < 4; j++) {
            int row = rowBase + wm + i * 16 + g;
            int col = colBase + wn + j * 8 + 2 * tg;
            float b0 = bias[col], b1 = bias[col + 1];
            float v00 = acc[i][j][0] + b0, v01 = acc[i][j][1] + b1;
            float v10 = acc[i][j][2] + b0, v11 = acc[i][j][3] + b1;
            if (FUSE) {
                float gc0 = gamma[col], gc1 = gamma[col + 1];
                size_t o0 = (size_t)row * EE + col;
                size_t o1 = (size_t)(row + 8) * EE + col;
                v00 = qin[o0]     + gc0 * (qn[o0]     + v00);
                v01 = qin[o0 + 1] + gc1 * (qn[o0 + 1] + v01);
                v10 = qin[o1]     + gc0 * (qn[o1]     + v10);
                v11 = qin[o1 + 1] + gc1 * (qn[o1 + 1] + v11);
            }
            *(float2*)&C[(size_t)row * N + col]       = make_float2(v00, v01);
            *(float2*)&C[(size_t)(row + 8) * N + col] = make_float2(v10, v11);
        }
    }
}

// ---------------- kernel: sampling locations + softmax weights ----------------
__global__ void locaw_kernel(const float* __restrict__ refp)
{
    int t = blockIdx.x * blockDim.x + threadIdx.x;
    if (t >= BQ * NH) return;
    int bq = t >> 3;
    int h  = t & 7;
    const float* raw = g_raw + (size_t)bq * NCAT;
    float rx = refp[bq * 2 + 0];
    float ry = refp[bq * 2 + 1];

    float* lp = g_loc + (size_t)t * NP * 2;
    float* ap = g_aw  + (size_t)t * NP;

    float lg[NP];
    float m = -1e30f;
#pragma unroll
    for (int p = 0; p < NP; p++) {
        lg[p] = raw[64 + h * 4 + p];
        m = fmaxf(m, lg[p]);
    }
    float sum = 0.f;
#pragma unroll
    for (int p = 0; p < NP; p++) { lg[p] = expf(lg[p] - m); sum += lg[p]; }
    float rinv = 1.0f / sum;
#pragma unroll
    for (int p = 0; p < NP; p++) {
        lp[p * 2 + 0] = rx + raw[h * 8 + p * 2 + 0] * (1.0f / (float)WF);
        lp[p * 2 + 1] = ry + raw[h * 8 + p * 2 + 1] * (1.0f / (float)HF);
        ap[p] = lg[p] * rinv;
    }
}

// ---------------- kernel: deformable bilinear sampling ----------------
// one warp per (b*NQ+q, h); lane covers d, d+32, d+64 of HD=96; output bf16
__global__ void msda_kernel()
{
    int gwarp = (blockIdx.x * blockDim.x + threadIdx.x) >> 5;
    int lane  = threadIdx.x & 31;
    if (gwarp >= BQ * NH) return;
    int bq = gwarp >> 3;
    int h  = gwarp & 7;
    int b  = bq >> 12;              // bq / NQ

    const float* lc    = g_loc + (size_t)gwarp * NP * 2;
    const float* awp   = g_aw  + (size_t)gwarp * NP;
    const float* vbase = g_value + (size_t)b * NV * EE + (size_t)h * HD;

    float acc0 = 0.f, acc1 = 0.f, acc2 = 0.f;
#pragma unroll
    for (int p = 0; p < NP; p++) {
        float x = lc[p * 2 + 0] * (float)WF - 0.5f;
        float y = lc[p * 2 + 1] * (float)HF - 0.5f;
        float a = awp[p];
        float fx = floorf(x), fy = floorf(y);
        int x0 = (int)fx, y0 = (int)fy;
        float tx = x - fx, ty = y - fy;
        float w00 = (1.f - tx) * (1.f - ty) * a;
        float w01 = tx * (1.f - ty) * a;
        float w10 = (1.f - tx) * ty * a;
        float w11 = tx * ty * a;
#pragma unroll
        for (int c = 0; c < 4; c++) {
            int xi = x0 + (c & 1);
            int yi = y0 + (c >> 1);
            float w = (c == 0) ? w00 : (c == 1) ? w01 : (c == 2) ? w10 : w11;
            if (xi >= 0 && xi < WF && yi >= 0 && yi < HF) {
                const float* v = vbase + (size_t)(yi * WF + xi) * EE;
                acc0 += w * v[lane];
                acc1 += w * v[lane + 32];
                acc2 += w * v[lane + 64];
            }
        }
    }
    __nv_bfloat16* o = g_msda_bf + (size_t)bq * EE + (size_t)h * HD;
    o[lane]      = __float2bfloat16(acc0);
    o[lane + 32] = __float2bfloat16(acc1);
    o[lane + 64] = __float2bfloat16(acc2);
}

// ---------------- launch ----------------
extern "C" void kernel_launch(void* const* d_in, const int* in_sizes, int n_in,
                              void* d_out, int out_size)
{
    (void)in_sizes; (void)n_in; (void)out_size;
    const float* query  = (const float*)d_in[0];
    const float* refp   = (const float*)d_in[1];
    const float* feat   = (const float*)d_in[2];
    const float* ln_q_w = (const float*)d_in[5];
    const float* ln_q_b = (const float*)d_in[6];
    const float* ln_f_w = (const float*)d_in[7];
    const float* ln_f_b = (const float*)d_in[8];
    const float* W_value= (const float*)d_in[9];
    const float* b_value= (const float*)d_in[10];
    const float* W_off  = (const float*)d_in[11];
    const float* b_off  = (const float*)d_in[12];
    const float* W_attn = (const float*)d_in[13];
    const float* b_attn = (const float*)d_in[14];
    const float* W_out  = (const float*)d_in[15];
    const float* b_out  = (const float*)d_in[16];
    const float* gamma  = (const float*)d_in[17];
    float* out = (float*)d_out;

    float *qnorm, *value, *raw, *bcat;
    __nv_bfloat16 *qnorm_bf, *fnorm_bf, *wv_bf, *wo_bf, *wcat_bf, *msda_bf;
    cudaGetSymbolAddress((void**)&qnorm,    g_qnorm);
    cudaGetSymbolAddress((void**)&qnorm_bf, g_qnorm_bf);
    cudaGetSymbolAddress((void**)&fnorm_bf, g_fnorm_bf);
    cudaGetSymbolAddress((void**)&value,    g_value);
    cudaGetSymbolAddress((void**)&raw,      g_raw);
    cudaGetSymbolAddress((void**)&wv_bf,    g_wv_bf);
    cudaGetSymbolAddress((void**)&wo_bf,    g_wo_bf);
    cudaGetSymbolAddress((void**)&wcat_bf,  g_wcat_bf);
    cudaGetSymbolAddress((void**)&bcat,     g_bcat);
    cudaGetSymbolAddress((void**)&msda_bf,  g_msda_bf);

    // 1. weight conversion + packing
    cvt_kernel<<<(EE * EE + 255) / 256, 256>>>(W_value, W_out, W_off, b_off, W_attn, b_attn);

    // 2. LayerNorms (query needs fp32 for epilogue; feat only bf16)
    ln_kernel<true ><<<BQ, 256>>>(query, ln_q_w, ln_q_b, qnorm, qnorm_bf);
    ln_kernel<false><<<BV, 256>>>(feat,  ln_f_w, ln_f_b, nullptr, fnorm_bf);

    // 3. value projection: [36864,768] = fnorm @ W_value (tensor cores)
    {
        dim3 g(EE / 128, BV / 128);
        gemm_bf16<false><<<g, 256>>>(fnorm_bf, wv_bf, b_value, value,
                                     BV, EE, EE, nullptr, nullptr, nullptr);
    }

    // 4. offset+attn projection: [16384,128] = qnorm @ wcat
    {
        dim3 g(NCAT / 128, BQ / 128);
        gemm_bf16<false><<<g, 256>>>(qnorm_bf, wcat_bf, bcat, raw,
                                     BQ, NCAT, EE, nullptr, nullptr, nullptr);
    }

    // 5. sampling locations + softmax attention weights
    locaw_kernel<<<(BQ * NH + 255) / 256, 256>>>(refp);

    // 6. deformable bilinear sampling: 1 warp per (b,q,h)
    msda_kernel<<<(BQ * NH * 32) / 256, 256>>>();

    // 7. out projection + fused residual: d_out = query + gamma*(qnorm + msda@W_out + b_out)
    {
        dim3 g(EE / 128, BQ / 128);
        gemm_bf16<true><<<g, 256>>>(msda_bf, wo_bf, b_out, out,
                                    BQ, EE, EE, qnorm, query, gamma);
    }
}

// round 6
// speedup vs baseline: 4.3275x; 1.2123x over previous
#include <cuda_runtime.h>
#include <cuda_bf16.h>
#include <cstdint>
#include <cstddef>

// ---------------- problem constants ----------------
#define BB   4
#define NQ   4096
#define NV   9216
#define EE   768
#define NH   8
#define NP   4
#define HD   96
#define HF   96
#define WF   96

#define BQ   (BB * NQ)   // 16384 query rows
#define BV   (BB * NV)   // 36864 feat rows
#define NCAT 128         // padded N for offset+attn projection

// ---------------- scratch (device globals) ----------------
__device__ __nv_bfloat16  g_qnorm_bf[(size_t)BQ * EE];
__device__ __nv_bfloat16  g_fnorm_bf[(size_t)BV * EE];
__device__ __nv_bfloat16  g_value_bf[(size_t)BV * EE];     // value proj (bf16)
__device__ float          g_raw     [(size_t)BQ * NCAT];
__device__ __nv_bfloat16  g_wv_bf   [(size_t)EE * EE];
__device__ __nv_bfloat16  g_wo_bf   [(size_t)EE * EE];
__device__ __nv_bfloat16  g_wcat_bf [(size_t)EE * NCAT];
__device__ float          g_bcat    [NCAT];
__device__ float          g_loc     [(size_t)BQ * NH * NP * 2];
__device__ float          g_aw      [(size_t)BQ * NH * NP];
__device__ __nv_bfloat16  g_msda_bf [(size_t)BQ * EE];

// ---------------- PTX helpers ----------------
__device__ __forceinline__ void ldsm4(uint32_t& r0, uint32_t& r1, uint32_t& r2, uint32_t& r3,
                                      uint32_t addr)
{
    asm volatile("ldmatrix.sync.aligned.m8n8.x4.shared.b16 {%0,%1,%2,%3}, [%4];"
                 : "=r"(r0), "=r"(r1), "=r"(r2), "=r"(r3) : "r"(addr));
}
__device__ __forceinline__ void ldsm4t(uint32_t& r0, uint32_t& r1, uint32_t& r2, uint32_t& r3,
                                       uint32_t addr)
{
    asm volatile("ldmatrix.sync.aligned.m8n8.x4.trans.shared.b16 {%0,%1,%2,%3}, [%4];"
                 : "=r"(r0), "=r"(r1), "=r"(r2), "=r"(r3) : "r"(addr));
}
__device__ __forceinline__ void mma16816(float* c, uint32_t a0, uint32_t a1, uint32_t a2,
                                         uint32_t a3, uint32_t b0, uint32_t b1)
{
    asm volatile("mma.sync.aligned.m16n8k16.row.col.f32.bf16.bf16.f32 "
                 "{%0,%1,%2,%3}, {%4,%5,%6,%7}, {%8,%9}, {%0,%1,%2,%3};"
                 : "+f"(c[0]), "+f"(c[1]), "+f"(c[2]), "+f"(c[3])
                 : "r"(a0), "r"(a1), "r"(a2), "r"(a3), "r"(b0), "r"(b1));
}
#define CP_ASYNC16(dst, src) \
    asm volatile("cp.async.cg.shared.global [%0], [%1], 16;" :: "r"(dst), "l"(src))
#define CP_COMMIT() asm volatile("cp.async.commit_group;" ::: "memory")
#define CP_WAIT1()  asm volatile("cp.async.wait_group 1;"  ::: "memory")

// ---------------- kernel: convert weights to bf16 + pack cat weights ----------------
__global__ void cvt_kernel(const float* __restrict__ Wv, const float* __restrict__ Wo,
                           const float* __restrict__ W_off, const float* __restrict__ b_off,
                           const float* __restrict__ W_attn, const float* __restrict__ b_attn)
{
    int idx = blockIdx.x * blockDim.x + threadIdx.x;
    if (idx < EE * EE) {
        g_wv_bf[idx] = __float2bfloat16(Wv[idx]);
        g_wo_bf[idx] = __float2bfloat16(Wo[idx]);
    }
    if (idx < EE * NCAT) {
        int k = idx / NCAT, n = idx % NCAT;
        float v = 0.f;
        if (n < 64)      v = W_off[k * 64 + n];
        else if (n < 96) v = W_attn[k * 32 + (n - 64)];
        g_wcat_bf[idx] = __float2bfloat16(v);
    }
    if (idx < NCAT) {
        float v = 0.f;
        if (idx < 64)      v = b_off[idx];
        else if (idx < 96) v = b_attn[idx - 64];
        g_bcat[idx] = v;
    }
}

// ---------------- kernel: LayerNorm over E=768, bf16 output ----------------
__global__ void ln_kernel(const float* __restrict__ x, const float* __restrict__ w,
                          const float* __restrict__ b, __nv_bfloat16* __restrict__ yb)
{
    __shared__ float rs[8], rq[8];
    int row = blockIdx.x;
    int t = threadIdx.x;                      // 256 threads
    const float* xr = x + (size_t)row * EE;
    float v0 = xr[t], v1 = xr[t + 256], v2 = xr[t + 512];
    float s = v0 + v1 + v2;
    float q = v0 * v0 + v1 * v1 + v2 * v2;
#pragma unroll
    for (int o = 16; o > 0; o >>= 1) {
        s += __shfl_down_sync(0xffffffffu, s, o);
        q += __shfl_down_sync(0xffffffffu, q, o);
    }
    int wid = t >> 5, lane = t & 31;
    if (lane == 0) { rs[wid] = s; rq[wid] = q; }
    __syncthreads();
    float S = 0.f, Q = 0.f;
#pragma unroll
    for (int i = 0; i < 8; i++) { S += rs[i]; Q += rq[i]; }
    const float inv = 1.0f / (float)EE;
    float mean = S * inv;
    float var  = Q * inv - mean * mean;
    float r    = rsqrtf(var + 1e-6f);
    size_t base = (size_t)row * EE;
    yb[base + t]       = __float2bfloat16((v0 - mean) * r * w[t]       + b[t]);
    yb[base + t + 256] = __float2bfloat16((v1 - mean) * r * w[t + 256] + b[t + 256]);
    yb[base + t + 512] = __float2bfloat16((v2 - mean) * r * w[t + 512] + b[t + 512]);
}

// ---------------- kernel: pipelined bf16 tensor-core GEMM ----------------
// Block tile BM x 128, warp tile WM x WN (8 warps), BK=32, 3-stage cp.async.
// OUT==0: fp32 C = A@B + bias
// OUT==1: bf16 C = A@B + bias
// OUT==2: fp32 C = qin + gamma*(bf16(qnb) + A@B + bias)   (N must equal EE)
template <int BM, int WM, int WN, int OUT>
__global__ void __launch_bounds__(256, 1)
gemm_bf16(const __nv_bfloat16* __restrict__ A, const __nv_bfloat16* __restrict__ Bm,
          const float* __restrict__ bias, void* __restrict__ Cout,
          int M, int N, int K,
          const __nv_bfloat16* __restrict__ qnb, const float* __restrict__ qin,
          const float* __restrict__ gamma)
{
    constexpr int BN = 128, BK = 32, STAGES = 3;
    constexpr int NWC = BN / WN;               // warps along N
    constexpr int MI = WM / 16, NI = WN / 8, NJ2 = WN / 16;
    constexpr int PA = BK + 8;                 // 40 bf16 (80B pitch, conflict-free)
    constexpr int PB = BN + 8;                 // 136 bf16 (272B pitch, conflict-free)
    constexpr int ASZ = BM * PA * 2;
    constexpr int BSZ = BK * PB * 2;
    constexpr int SB  = ASZ + BSZ;

    extern __shared__ char smem[];
    uint32_t smemU = (uint32_t)__cvta_generic_to_shared(smem);

    int tid = threadIdx.x, warp = tid >> 5, lane = tid & 31;
    int rowBase = blockIdx.y * BM;
    int colBase = blockIdx.x * BN;
    int wm = (warp / NWC) * WM;
    int wn = (warp % NWC) * WN;

    // cp.async staging coords
    int ar = tid >> 2, ac = (tid & 3) * 8;     // A: 64 rows / round, 4 x 16B per row
    int br = tid >> 4, bc = (tid & 15) * 8;    // B: 16 rows / round, 16 x 16B per row
    const __nv_bfloat16* Ag = A  + (size_t)(rowBase + ar) * K + ac;
    const __nv_bfloat16* Bg = Bm + (size_t)br * N + colBase + bc;
    uint32_t aDst = (uint32_t)(ar * PA + ac) * 2;
    uint32_t bDst = (uint32_t)(br * PB + bc) * 2;

    // ldmatrix offsets within a stage
    uint32_t aLd[MI], bLd[NJ2];
#pragma unroll
    for (int i = 0; i < MI; i++)
        aLd[i] = (uint32_t)((wm + i * 16 + (lane & 15)) * PA + (lane >> 4) * 8) * 2;
#pragma unroll
    for (int j = 0; j < NJ2; j++)
        bLd[j] = (uint32_t)((lane & 15) * PB + wn + j * 16 + (lane >> 4) * 8) * 2;

    float acc[MI][NI][4];
#pragma unroll
    for (int i = 0; i < MI; i++)
#pragma unroll
        for (int j = 0; j < NI; j++)
#pragma unroll
            for (int v = 0; v < 4; v++) acc[i][j][v] = 0.f;

    const int KT = K / BK;

    auto issue = [&](int kt, int s) {
        uint32_t aB = smemU + s * SB + aDst;
        uint32_t bB = smemU + s * SB + ASZ + bDst;
#pragma unroll
        for (int r = 0; r < BM / 64; r++)
            CP_ASYNC16(aB + r * 64 * PA * 2, Ag + (size_t)(r * 64) * K + kt);
#pragma unroll
        for (int r = 0; r < 2; r++)
            CP_ASYNC16(bB + r * 16 * PB * 2, Bg + (size_t)(kt + r * 16) * N);
        CP_COMMIT();
    };

    // prologue: stages 0..1
#pragma unroll
    for (int s = 0; s < STAGES - 1; s++) issue(s * BK, s);

    for (int t = 0; t < KT; t++) {
        CP_WAIT1();
        __syncthreads();
        int nk = t + STAGES - 1;
        if (nk < KT) issue(nk * BK, nk % STAGES);
        else CP_COMMIT();   // empty group keeps wait count uniform

        uint32_t aB = smemU + (t % STAGES) * SB;
        uint32_t bB = aB + ASZ;
#pragma unroll
        for (int ks = 0; ks < 2; ks++) {
            uint32_t af[MI][4], bf[NJ2][4];
#pragma unroll
            for (int i = 0; i < MI; i++)
                ldsm4(af[i][0], af[i][1], af[i][2], af[i][3], aB + aLd[i] + ks * 32);
#pragma unroll
            for (int j = 0; j < NJ2; j++)
                ldsm4t(bf[j][0], bf[j][1], bf[j][2], bf[j][3],
                       bB + bLd[j] + ks * 16 * PB * 2);
#pragma unroll
            for (int i = 0; i < MI; i++)
#pragma unroll
                for (int j = 0; j < NI; j++)
                    mma16816(acc[i][j], af[i][0], af[i][1], af[i][2], af[i][3],
                             bf[j >> 1][(j & 1) * 2], bf[j >> 1][(j & 1) * 2 + 1]);
        }
    }

    // epilogue
    int g = lane >> 2, tg = lane & 3;
#pragma unroll
    for (int i = 0; i < MI; i++) {
#pragma unroll
        for (int j = 0; j < NI; j++) {
            int row = rowBase + wm + i * 16 + g;
            int col = colBase + wn + j * 8 + tg * 2;
            float b0 = bias[col], b1 = bias[col + 1];
            float v00 = acc[i][j][0] + b0, v01 = acc[i][j][1] + b1;
            float v10 = acc[i][j][2] + b0, v11 = acc[i][j][3] + b1;
            if (OUT == 2) {
                float gc0 = gamma[col], gc1 = gamma[col + 1];
                size_t o0 = (size_t)row * EE + col;
                size_t o1 = (size_t)(row + 8) * EE + col;
                float2 q0 = *(const float2*)&qin[o0];
                float2 q1 = *(const float2*)&qin[o1];
                __nv_bfloat162 n0 = *(const __nv_bfloat162*)&qnb[o0];
                __nv_bfloat162 n1 = *(const __nv_bfloat162*)&qnb[o1];
                v00 = q0.x + gc0 * (__bfloat162float(n0.x) + v00);
                v01 = q0.y + gc1 * (__bfloat162float(n0.y) + v01);
                v10 = q1.x + gc0 * (__bfloat162float(n1.x) + v10);
                v11 = q1.y + gc1 * (__bfloat162float(n1.y) + v11);
            }
            if (OUT == 1) {
                __nv_bfloat16* C = (__nv_bfloat16*)Cout;
                *(__nv_bfloat162*)&C[(size_t)row * N + col] =
                    __floats2bfloat162_rn(v00, v01);
                *(__nv_bfloat162*)&C[(size_t)(row + 8) * N + col] =
                    __floats2bfloat162_rn(v10, v11);
            } else {
                float* C = (float*)Cout;
                *(float2*)&C[(size_t)row * N + col]       = make_float2(v00, v01);
                *(float2*)&C[(size_t)(row + 8) * N + col] = make_float2(v10, v11);
            }
        }
    }
}

// ---------------- kernel: sampling locations + softmax weights ----------------
__global__ void locaw_kernel(const float* __restrict__ refp)
{
    int t = blockIdx.x * blockDim.x + threadIdx.x;
    if (t >= BQ * NH) return;
    int bq = t >> 3;
    int h  = t & 7;
    const float* raw = g_raw + (size_t)bq * NCAT;
    float rx = refp[bq * 2 + 0];
    float ry = refp[bq * 2 + 1];

    float* lp = g_loc + (size_t)t * NP * 2;
    float* ap = g_aw  + (size_t)t * NP;

    float lg[NP];
    float m = -1e30f;
#pragma unroll
    for (int p = 0; p < NP; p++) {
        lg[p] = raw[64 + h * 4 + p];
        m = fmaxf(m, lg[p]);
    }
    float sum = 0.f;
#pragma unroll
    for (int p = 0; p < NP; p++) { lg[p] = expf(lg[p] - m); sum += lg[p]; }
    float rinv = 1.0f / sum;
#pragma unroll
    for (int p = 0; p < NP; p++) {
        lp[p * 2 + 0] = rx + raw[h * 8 + p * 2 + 0] * (1.0f / (float)WF);
        lp[p * 2 + 1] = ry + raw[h * 8 + p * 2 + 1] * (1.0f / (float)HF);
        ap[p] = lg[p] * rinv;
    }
}

// ---------------- kernel: deformable bilinear sampling (bf16 value) ----------------
// one warp per (b*NQ+q, h); lane covers d, d+32, d+64 of HD=96
__global__ void msda_kernel()
{
    int gwarp = (blockIdx.x * blockDim.x + threadIdx.x) >> 5;
    int lane  = threadIdx.x & 31;
    if (gwarp >= BQ * NH) return;
    int bq = gwarp >> 3;
    int h  = gwarp & 7;
    int b  = bq >> 12;              // bq / NQ

    const float* lc    = g_loc + (size_t)gwarp * NP * 2;
    const float* awp   = g_aw  + (size_t)gwarp * NP;
    const __nv_bfloat16* vbase = g_value_bf + (size_t)b * NV * EE + (size_t)h * HD;

    float acc0 = 0.f, acc1 = 0.f, acc2 = 0.f;
#pragma unroll
    for (int p = 0; p < NP; p++) {
        float x = lc[p * 2 + 0] * (float)WF - 0.5f;
        float y = lc[p * 2 + 1] * (float)HF - 0.5f;
        float a = awp[p];
        float fx = floorf(x), fy = floorf(y);
        int x0 = (int)fx, y0 = (int)fy;
        float tx = x - fx, ty = y - fy;
        float w00 = (1.f - tx) * (1.f - ty) * a;
        float w01 = tx * (1.f - ty) * a;
        float w10 = (1.f - tx) * ty * a;
        float w11 = tx * ty * a;
#pragma unroll
        for (int c = 0; c < 4; c++) {
            int xi = x0 + (c & 1);
            int yi = y0 + (c >> 1);
            float w = (c == 0) ? w00 : (c == 1) ? w01 : (c == 2) ? w10 : w11;
            if (xi >= 0 && xi < WF && yi >= 0 && yi < HF) {
                const __nv_bfloat16* v = vbase + (size_t)(yi * WF + xi) * EE;
                acc0 += w * __bfloat162float(v[lane]);
                acc1 += w * __bfloat162float(v[lane + 32]);
                acc2 += w * __bfloat162float(v[lane + 64]);
            }
        }
    }
    __nv_bfloat16* o = g_msda_bf + (size_t)bq * EE + (size_t)h * HD;
    o[lane]      = __float2bfloat16(acc0);
    o[lane + 32] = __float2bfloat16(acc1);
    o[lane + 64] = __float2bfloat16(acc2);
}

// ---------------- launch ----------------
extern "C" void kernel_launch(void* const* d_in, const int* in_sizes, int n_in,
                              void* d_out, int out_size)
{
    (void)in_sizes; (void)n_in; (void)out_size;
    const float* query  = (const float*)d_in[0];
    const float* refp   = (const float*)d_in[1];
    const float* feat   = (const float*)d_in[2];
    const float* ln_q_w = (const float*)d_in[5];
    const float* ln_q_b = (const float*)d_in[6];
    const float* ln_f_w = (const float*)d_in[7];
    const float* ln_f_b = (const float*)d_in[8];
    const float* W_value= (const float*)d_in[9];
    const float* b_value= (const float*)d_in[10];
    const float* W_off  = (const float*)d_in[11];
    const float* b_off  = (const float*)d_in[12];
    const float* W_attn = (const float*)d_in[13];
    const float* b_attn = (const float*)d_in[14];
    const float* W_out  = (const float*)d_in[15];
    const float* b_out  = (const float*)d_in[16];
    const float* gamma  = (const float*)d_in[17];
    float* out = (float*)d_out;

    float *raw, *bcat;
    __nv_bfloat16 *qnorm_bf, *fnorm_bf, *value_bf, *wv_bf, *wo_bf, *wcat_bf, *msda_bf;
    cudaGetSymbolAddress((void**)&qnorm_bf, g_qnorm_bf);
    cudaGetSymbolAddress((void**)&fnorm_bf, g_fnorm_bf);
    cudaGetSymbolAddress((void**)&value_bf, g_value_bf);
    cudaGetSymbolAddress((void**)&raw,      g_raw);
    cudaGetSymbolAddress((void**)&wv_bf,    g_wv_bf);
    cudaGetSymbolAddress((void**)&wo_bf,    g_wo_bf);
    cudaGetSymbolAddress((void**)&wcat_bf,  g_wcat_bf);
    cudaGetSymbolAddress((void**)&bcat,     g_bcat);
    cudaGetSymbolAddress((void**)&msda_bf,  g_msda_bf);

    // dynamic smem sizes: 3 stages * (BM*40 + 32*136) * 2 bytes
    const int SMEM_BIG   = 3 * (256 * 40 * 2 + 32 * 136 * 2);   // 87552
    const int SMEM_SMALL = 3 * (128 * 40 * 2 + 32 * 136 * 2);   // 56832
    cudaFuncSetAttribute(gemm_bf16<256, 64, 64, 1>,
                         cudaFuncAttributeMaxDynamicSharedMemorySize, SMEM_BIG);
    cudaFuncSetAttribute(gemm_bf16<256, 64, 64, 2>,
                         cudaFuncAttributeMaxDynamicSharedMemorySize, SMEM_BIG);
    cudaFuncSetAttribute(gemm_bf16<128, 64, 32, 0>,
                         cudaFuncAttributeMaxDynamicSharedMemorySize, SMEM_SMALL);

    // 1. weight conversion + packing
    cvt_kernel<<<(EE * EE + 255) / 256, 256>>>(W_value, W_out, W_off, b_off, W_attn, b_attn);

    // 2. LayerNorms (bf16 outputs)
    ln_kernel<<<BQ, 256>>>(query, ln_q_w, ln_q_b, qnorm_bf);
    ln_kernel<<<BV, 256>>>(feat,  ln_f_w, ln_f_b, fnorm_bf);

    // 3. value projection: [36864,768] bf16 out
    {
        dim3 g(EE / 128, BV / 256);
        gemm_bf16<256, 64, 64, 1><<<g, 256, SMEM_BIG>>>(
            fnorm_bf, wv_bf, b_value, value_bf, BV, EE, EE, nullptr, nullptr, nullptr);
    }

    // 4. offset+attn projection: [16384,128] fp32 out
    {
        dim3 g(NCAT / 128, BQ / 128);
        gemm_bf16<128, 64, 32, 0><<<g, 256, SMEM_SMALL>>>(
            qnorm_bf, wcat_bf, bcat, raw, BQ, NCAT, EE, nullptr, nullptr, nullptr);
    }

    // 5. sampling locations + softmax attention weights
    locaw_kernel<<<(BQ * NH + 255) / 256, 256>>>(refp);

    // 6. deformable bilinear sampling: 1 warp per (b,q,h)
    msda_kernel<<<(BQ * NH * 32) / 256, 256>>>();

    // 7. out projection + fused residual: d_out = query + gamma*(qnorm + msda@W_out + b_out)
    {
        dim3 g(EE / 128, BQ / 256);
        gemm_bf16<256, 64, 64, 2><<<g, 256, SMEM_BIG>>>(
            msda_bf, wo_bf, b_out, out, BQ, EE, EE, qnorm_bf, query, gamma);
    }
}

// round 8
// speedup vs baseline: 4.7154x; 1.0896x over previous
#include <cuda_runtime.h>
#include <cuda_bf16.h>
#include <cstdint>
#include <cstddef>

// ---------------- problem constants ----------------
#define BB   4
#define NQ   4096
#define NV   9216
#define EE   768
#define NH   8
#define NP   4
#define HD   96
#define HF   96
#define WF   96

#define BQ   (BB * NQ)   // 16384 query rows
#define BV   (BB * NV)   // 36864 feat rows
#define NCAT 128         // padded N for offset+attn projection

// ---------------- scratch (device globals) ----------------
__device__ __nv_bfloat16  g_qnorm_bf[(size_t)BQ * EE];
__device__ __nv_bfloat16  g_fnorm_bf[(size_t)BV * EE];
__device__ __nv_bfloat16  g_value_bf[(size_t)BV * EE];     // value proj (bf16)
__device__ float          g_raw     [(size_t)BQ * NCAT];
__device__ __nv_bfloat16  g_wv_bf   [(size_t)EE * EE];
__device__ __nv_bfloat16  g_wo_bf   [(size_t)EE * EE];
__device__ __nv_bfloat16  g_wcat_bf [(size_t)EE * NCAT];
__device__ float          g_bcat    [NCAT];
__device__ __nv_bfloat16  g_msda_bf [(size_t)BQ * EE];

// ---------------- PTX helpers ----------------
__device__ __forceinline__ void ldsm4(uint32_t& r0, uint32_t& r1, uint32_t& r2, uint32_t& r3,
                                      uint32_t addr)
{
    asm volatile("ldmatrix.sync.aligned.m8n8.x4.shared.b16 {%0,%1,%2,%3}, [%4];"
                 : "=r"(r0), "=r"(r1), "=r"(r2), "=r"(r3) : "r"(addr));
}
__device__ __forceinline__ void ldsm4t(uint32_t& r0, uint32_t& r1, uint32_t& r2, uint32_t& r3,
                                       uint32_t addr)
{
    asm volatile("ldmatrix.sync.aligned.m8n8.x4.trans.shared.b16 {%0,%1,%2,%3}, [%4];"
                 : "=r"(r0), "=r"(r1), "=r"(r2), "=r"(r3) : "r"(addr));
}
__device__ __forceinline__ void mma16816(float* c, uint32_t a0, uint32_t a1, uint32_t a2,
                                         uint32_t a3, uint32_t b0, uint32_t b1)
{
    asm volatile("mma.sync.aligned.m16n8k16.row.col.f32.bf16.bf16.f32 "
                 "{%0,%1,%2,%3}, {%4,%5,%6,%7}, {%8,%9}, {%0,%1,%2,%3};"
                 : "+f"(c[0]), "+f"(c[1]), "+f"(c[2]), "+f"(c[3])
                 : "r"(a0), "r"(a1), "r"(a2), "r"(a3), "r"(b0), "r"(b1));
}
#define CP_ASYNC16(dst, src) \
    asm volatile("cp.async.cg.shared.global [%0], [%1], 16;" :: "r"(dst), "l"(src))
#define CP_COMMIT() asm volatile("cp.async.commit_group;" ::: "memory")
#define CP_WAIT1()  asm volatile("cp.async.wait_group 1;"  ::: "memory")

// ---------------- kernel: convert weights to bf16 + pack cat weights ----------------
__global__ void cvt_kernel(const float* __restrict__ Wv, const float* __restrict__ Wo,
                           const float* __restrict__ W_off, const float* __restrict__ b_off,
                           const float* __restrict__ W_attn, const float* __restrict__ b_attn)
{
    int idx = blockIdx.x * blockDim.x + threadIdx.x;
    if (idx < EE * EE) {
        g_wv_bf[idx] = __float2bfloat16(Wv[idx]);
        g_wo_bf[idx] = __float2bfloat16(Wo[idx]);
    }
    if (idx < EE * NCAT) {
        int k = idx / NCAT, n = idx % NCAT;
        float v = 0.f;
        if (n < 64)      v = W_off[k * 64 + n];
        else if (n < 96) v = W_attn[k * 32 + (n - 64)];
        g_wcat_bf[idx] = __float2bfloat16(v);
    }
    if (idx < NCAT) {
        float v = 0.f;
        if (idx < 64)      v = b_off[idx];
        else if (idx < 96) v = b_attn[idx - 64];
        g_bcat[idx] = v;
    }
}

// ---------------- kernel: LayerNorm over E=768, bf16 output ----------------
__global__ void ln_kernel(const float* __restrict__ x, const float* __restrict__ w,
                          const float* __restrict__ b, __nv_bfloat16* __restrict__ yb)
{
    __shared__ float rs[8], rq[8];
    int row = blockIdx.x;
    int t = threadIdx.x;                      // 256 threads
    const float* xr = x + (size_t)row * EE;
    float v0 = xr[t], v1 = xr[t + 256], v2 = xr[t + 512];
    float s = v0 + v1 + v2;
    float q = v0 * v0 + v1 * v1 + v2 * v2;
#pragma unroll
    for (int o = 16; o > 0; o >>= 1) {
        s += __shfl_down_sync(0xffffffffu, s, o);
        q += __shfl_down_sync(0xffffffffu, q, o);
    }
    int wid = t >> 5, lane = t & 31;
    if (lane == 0) { rs[wid] = s; rq[wid] = q; }
    __syncthreads();
    float S = 0.f, Q = 0.f;
#pragma unroll
    for (int i = 0; i < 8; i++) { S += rs[i]; Q += rq[i]; }
    const float inv = 1.0f / (float)EE;
    float mean = S * inv;
    float var  = Q * inv - mean * mean;
    float r    = rsqrtf(var + 1e-6f);
    size_t base = (size_t)row * EE;
    yb[base + t]       = __float2bfloat16((v0 - mean) * r * w[t]       + b[t]);
    yb[base + t + 256] = __float2bfloat16((v1 - mean) * r * w[t + 256] + b[t + 256]);
    yb[base + t + 512] = __float2bfloat16((v2 - mean) * r * w[t + 512] + b[t + 512]);
}

// ---------------- kernel: pipelined bf16 tensor-core GEMM ----------------
// Block tile 128x128, warp tile 64x32 (8 warps), BK=32, 3-stage cp.async.
// Forced 2 CTAs/SM via __launch_bounds__ for sync-shadow overlap.
// OUT==0: fp32 C = A@B + bias
// OUT==1: bf16 C = A@B + bias
// OUT==2: fp32 C = qin + gamma*(bf16(qnb) + A@B + bias)   (N must equal EE)
template <int OUT>
__global__ void __launch_bounds__(256, 2)
gemm_bf16(const __nv_bfloat16* __restrict__ A, const __nv_bfloat16* __restrict__ Bm,
          const float* __restrict__ bias, void* __restrict__ Cout,
          int M, int N, int K,
          const __nv_bfloat16* __restrict__ qnb, const float* __restrict__ qin,
          const float* __restrict__ gamma)
{
    constexpr int BM = 128, BN = 128, BK = 32, STAGES = 3;
    constexpr int WM = 64, WN = 32;
    constexpr int NWC = BN / WN;               // 4 warps along N
    constexpr int MI = WM / 16, NI = WN / 8, NJ2 = WN / 16;   // 4, 4, 2
    constexpr int PA = BK + 8;                 // 40 bf16 (80B pitch)
    constexpr int PB = BN + 8;                 // 136 bf16 (272B pitch)
    constexpr int ASZ = BM * PA * 2;
    constexpr int BSZ = BK * PB * 2;
    constexpr int SB  = ASZ + BSZ;

    extern __shared__ char smem[];
    uint32_t smemU = (uint32_t)__cvta_generic_to_shared(smem);

    int tid = threadIdx.x, warp = tid >> 5, lane = tid & 31;
    int rowBase = blockIdx.y * BM;
    int colBase = blockIdx.x * BN;
    int wm = (warp / NWC) * WM;
    int wn = (warp % NWC) * WN;

    // cp.async staging coords
    int ar = tid >> 2, ac = (tid & 3) * 8;     // A: 64 rows / round
    int br = tid >> 4, bc = (tid & 15) * 8;    // B: 16 rows / round
    const __nv_bfloat16* Ag = A  + (size_t)(rowBase + ar) * K + ac;
    const __nv_bfloat16* Bg = Bm + (size_t)br * N + colBase + bc;
    uint32_t aDst = (uint32_t)(ar * PA + ac) * 2;
    uint32_t bDst = (uint32_t)(br * PB + bc) * 2;

    // ldmatrix offsets within a stage
    uint32_t aLd[MI], bLd[NJ2];
#pragma unroll
    for (int i = 0; i < MI; i++)
        aLd[i] = (uint32_t)((wm + i * 16 + (lane & 15)) * PA + (lane >> 4) * 8) * 2;
#pragma unroll
    for (int j = 0; j < NJ2; j++)
        bLd[j] = (uint32_t)((lane & 15) * PB + wn + j * 16 + (lane >> 4) * 8) * 2;

    float acc[MI][NI][4];
#pragma unroll
    for (int i = 0; i < MI; i++)
#pragma unroll
        for (int j = 0; j < NI; j++)
#pragma unroll
            for (int v = 0; v < 4; v++) acc[i][j][v] = 0.f;

    const int KT = K / BK;

    auto issue = [&](int kt, int s) {
        uint32_t aB = smemU + s * SB + aDst;
        uint32_t bB = smemU + s * SB + ASZ + bDst;
#pragma unroll
        for (int r = 0; r < BM / 64; r++)
            CP_ASYNC16(aB + r * 64 * PA * 2, Ag + (size_t)(r * 64) * K + kt);
#pragma unroll
        for (int r = 0; r < 2; r++)
            CP_ASYNC16(bB + r * 16 * PB * 2, Bg + (size_t)(kt + r * 16) * N);
        CP_COMMIT();
    };

    // prologue: stages 0..1
#pragma unroll
    for (int s = 0; s < STAGES - 1; s++) issue(s * BK, s);

    for (int t = 0; t < KT; t++) {
        CP_WAIT1();
        __syncthreads();
        int nk = t + STAGES - 1;
        if (nk < KT) issue(nk * BK, nk % STAGES);
        else CP_COMMIT();   // empty group keeps wait count uniform

        uint32_t aB = smemU + (t % STAGES) * SB;
        uint32_t bB = aB + ASZ;
#pragma unroll
        for (int ks = 0; ks < 2; ks++) {
            uint32_t af[MI][4], bf[NJ2][4];
#pragma unroll
            for (int i = 0; i < MI; i++)
                ldsm4(af[i][0], af[i][1], af[i][2], af[i][3], aB + aLd[i] + ks * 32);
#pragma unroll
            for (int j = 0; j < NJ2; j++)
                ldsm4t(bf[j][0], bf[j][1], bf[j][2], bf[j][3],
                       bB + bLd[j] + ks * 16 * PB * 2);
#pragma unroll
            for (int i = 0; i < MI; i++)
#pragma unroll
                for (int j = 0; j < NI; j++)
                    mma16816(acc[i][j], af[i][0], af[i][1], af[i][2], af[i][3],
                             bf[j >> 1][(j & 1) * 2], bf[j >> 1][(j & 1) * 2 + 1]);
        }
    }

    // epilogue
    int g = lane >> 2, tg = lane & 3;
#pragma unroll
    for (int i = 0; i < MI; i++) {
#pragma unroll
        for (int j = 0; j < NI; j++) {
            int row = rowBase + wm + i * 16 + g;
            int col = colBase + wn + j * 8 + tg * 2;
            float b0 = bias[col], b1 = bias[col + 1];
            float v00 = acc[i][j][0] + b0, v01 = acc[i][j][1] + b1;
            float v10 = acc[i][j][2] + b0, v11 = acc[i][j][3] + b1;
            if (OUT == 2) {
                float gc0 = gamma[col], gc1 = gamma[col + 1];
                size_t o0 = (size_t)row * EE + col;
                size_t o1 = (size_t)(row + 8) * EE + col;
                float2 q0 = *(const float2*)&qin[o0];
                float2 q1 = *(const float2*)&qin[o1];
                __nv_bfloat162 n0 = *(const __nv_bfloat162*)&qnb[o0];
                __nv_bfloat162 n1 = *(const __nv_bfloat162*)&qnb[o1];
                v00 = q0.x + gc0 * (__bfloat162float(n0.x) + v00);
                v01 = q0.y + gc1 * (__bfloat162float(n0.y) + v01);
                v10 = q1.x + gc0 * (__bfloat162float(n1.x) + v10);
                v11 = q1.y + gc1 * (__bfloat162float(n1.y) + v11);
            }
            if (OUT == 1) {
                __nv_bfloat16* C = (__nv_bfloat16*)Cout;
                *(__nv_bfloat162*)&C[(size_t)row * N + col] =
                    __floats2bfloat162_rn(v00, v01);
                *(__nv_bfloat162*)&C[(size_t)(row + 8) * N + col] =
                    __floats2bfloat162_rn(v10, v11);
            } else {
                float* C = (float*)Cout;
                *(float2*)&C[(size_t)row * N + col]       = make_float2(v00, v01);
                *(float2*)&C[(size_t)(row + 8) * N + col] = make_float2(v10, v11);
            }
        }
    }
}

// ---------------- kernel: fused softmax + deformable bilinear sampling ----------------
// one warp per (b*NQ+q, h); every lane redundantly computes the 4-way softmax
// and sampling locations from g_raw (uniform loads), then samples bf16 value.
__global__ void msda_kernel(const float* __restrict__ refp)
{
    int gwarp = (blockIdx.x * blockDim.x + threadIdx.x) >> 5;
    int lane  = threadIdx.x & 31;
    if (gwarp >= BQ * NH) return;
    int bq = gwarp >> 3;
    int h  = gwarp & 7;
    int b  = bq >> 12;              // bq / NQ

    const float* raw = g_raw + (size_t)bq * NCAT;
    float rx = refp[bq * 2 + 0];
    float ry = refp[bq * 2 + 1];

    // softmax over the 4 logits for this head
    float lg[NP];
    float m = -1e30f;
#pragma unroll
    for (int p = 0; p < NP; p++) {
        lg[p] = raw[64 + h * 4 + p];
        m = fmaxf(m, lg[p]);
    }
    float sum = 0.f;
#pragma unroll
    for (int p = 0; p < NP; p++) { lg[p] = expf(lg[p] - m); sum += lg[p]; }
    float rinv = 1.0f / sum;

    const __nv_bfloat16* vbase = g_value_bf + (size_t)b * NV * EE + (size_t)h * HD;

    float acc0 = 0.f, acc1 = 0.f, acc2 = 0.f;
#pragma unroll
    for (int p = 0; p < NP; p++) {
        float lx = rx + raw[h * 8 + p * 2 + 0] * (1.0f / (float)WF);
        float ly = ry + raw[h * 8 + p * 2 + 1] * (1.0f / (float)HF);
        float x = lx * (float)WF - 0.5f;
        float y = ly * (float)HF - 0.5f;
        float a = lg[p] * rinv;
        float fx = floorf(x), fy = floorf(y);
        int x0 = (int)fx, y0 = (int)fy;
        float tx = x - fx, ty = y - fy;
        float w00 = (1.f - tx) * (1.f - ty) * a;
        float w01 = tx * (1.f - ty) * a;
        float w10 = (1.f - tx) * ty * a;
        float w11 = tx * ty * a;
#pragma unroll
        for (int c = 0; c < 4; c++) {
            int xi = x0 + (c & 1);
            int yi = y0 + (c >> 1);
            float w = (c == 0) ? w00 : (c == 1) ? w01 : (c == 2) ? w10 : w11;
            if (xi >= 0 && xi < WF && yi >= 0 && yi < HF) {
                const __nv_bfloat16* v = vbase + (size_t)(yi * WF + xi) * EE;
                acc0 += w * __bfloat162float(v[lane]);
                acc1 += w * __bfloat162float(v[lane + 32]);
                acc2 += w * __bfloat162float(v[lane + 64]);
            }
        }
    }
    __nv_bfloat16* o = g_msda_bf + (size_t)bq * EE + (size_t)h * HD;
    o[lane]      = __float2bfloat16(acc0);
    o[lane + 32] = __float2bfloat16(acc1);
    o[lane + 64] = __float2bfloat16(acc2);
}

// ---------------- launch ----------------
extern "C" void kernel_launch(void* const* d_in, const int* in_sizes, int n_in,
                              void* d_out, int out_size)
{
    (void)in_sizes; (void)n_in; (void)out_size;
    const float* query  = (const float*)d_in[0];
    const float* refp   = (const float*)d_in[1];
    const float* feat   = (const float*)d_in[2];
    const float* ln_q_w = (const float*)d_in[5];
    const float* ln_q_b = (const float*)d_in[6];
    const float* ln_f_w = (const float*)d_in[7];
    const float* ln_f_b = (const float*)d_in[8];
    const float* W_value= (const float*)d_in[9];
    const float* b_value= (const float*)d_in[10];
    const float* W_off  = (const float*)d_in[11];
    const float* b_off  = (const float*)d_in[12];
    const float* W_attn = (const float*)d_in[13];
    const float* b_attn = (const float*)d_in[14];
    const float* W_out  = (const float*)d_in[15];
    const float* b_out  = (const float*)d_in[16];
    const float* gamma  = (const float*)d_in[17];
    float* out = (float*)d_out;

    float *raw, *bcat;
    __nv_bfloat16 *qnorm_bf, *fnorm_bf, *value_bf, *wv_bf, *wo_bf, *wcat_bf, *msda_bf;
    cudaGetSymbolAddress((void**)&qnorm_bf, g_qnorm_bf);
    cudaGetSymbolAddress((void**)&fnorm_bf, g_fnorm_bf);
    cudaGetSymbolAddress((void**)&value_bf, g_value_bf);
    cudaGetSymbolAddress((void**)&raw,      g_raw);
    cudaGetSymbolAddress((void**)&wv_bf,    g_wv_bf);
    cudaGetSymbolAddress((void**)&wo_bf,    g_wo_bf);
    cudaGetSymbolAddress((void**)&wcat_bf,  g_wcat_bf);
    cudaGetSymbolAddress((void**)&bcat,     g_bcat);
    cudaGetSymbolAddress((void**)&msda_bf,  g_msda_bf);

    // dyn smem: 3 stages * (128*40 + 32*136) * 2 bytes = 56832
    const int SMEM = 3 * (128 * 40 * 2 + 32 * 136 * 2);
    cudaFuncSetAttribute(gemm_bf16<0>, cudaFuncAttributeMaxDynamicSharedMemorySize, SMEM);
    cudaFuncSetAttribute(gemm_bf16<1>, cudaFuncAttributeMaxDynamicSharedMemorySize, SMEM);
    cudaFuncSetAttribute(gemm_bf16<2>, cudaFuncAttributeMaxDynamicSharedMemorySize, SMEM);

    // 1. weight conversion + packing
    cvt_kernel<<<(EE * EE + 255) / 256, 256>>>(W_value, W_out, W_off, b_off, W_attn, b_attn);

    // 2. LayerNorms (bf16 outputs)
    ln_kernel<<<BQ, 256>>>(query, ln_q_w, ln_q_b, qnorm_bf);
    ln_kernel<<<BV, 256>>>(feat,  ln_f_w, ln_f_b, fnorm_bf);

    // 3. value projection: [36864,768] bf16 out
    gemm_bf16<1><<<dim3(EE / 128, BV / 128), 256, SMEM>>>(
        fnorm_bf, wv_bf, b_value, value_bf, BV, EE, EE, nullptr, nullptr, nullptr);

    // 4. offset+attn projection: [16384,128] fp32 out
    gemm_bf16<0><<<dim3(NCAT / 128, BQ / 128), 256, SMEM>>>(
        qnorm_bf, wcat_bf, bcat, raw, BQ, NCAT, EE, nullptr, nullptr, nullptr);

    // 5. fused softmax + deformable bilinear sampling: 1 warp per (b,q,h)
    msda_kernel<<<(BQ * NH * 32) / 256, 256>>>(refp);

    // 6. out projection + fused residual: d_out = query + gamma*(qnorm + msda@W_out + b_out)
    gemm_bf16<2><<<dim3(EE / 128, BQ / 128), 256, SMEM>>>(
        msda_bf, wo_bf, b_out, out, BQ, EE, EE, qnorm_bf, query, gamma);
}